// round 1
// baseline (speedup 1.0000x reference)
#include <cuda_runtime.h>
#include <cstdint>

// GARCH(1,1) path generation.
// z: (N, T, D) fp32, params omega/alpha/beta/mu/sigma2_0: (D,) fp32.
// sigma2_t = omega + sigma2_{t-1} * (alpha*z_{t-1}^2 + beta)   [eps2 folded in]
// x_t = mu + sqrt(max(sigma2_t, 1e-12)) * z_t
//
// One thread per chain n, both d packed into f32x2 ops. Unroll T by 4 so each
// thread reads/writes its own aligned 32B sector per iteration. Register
// prefetch ring (depth 4 iters = 8 LDG.128 in flight) to hide DRAM latency
// at low occupancy (1024 warps total).

#define GARCH_N 32768
#define GARCH_T 2048
#define GARCH_D 2
#define NIT (GARCH_T / 4)   // 512 iterations of 4 time steps
#define PF 4                // prefetch distance in iterations

typedef unsigned long long u64;

__device__ __forceinline__ u64 pk2(float lo, float hi) {
    u64 r; asm("mov.b64 %0, {%1, %2};" : "=l"(r) : "f"(lo), "f"(hi)); return r;
}
__device__ __forceinline__ void upk2(u64 v, float& lo, float& hi) {
    asm("mov.b64 {%0, %1}, %2;" : "=f"(lo), "=f"(hi) : "l"(v));
}
__device__ __forceinline__ u64 fma2(u64 a, u64 b, u64 c) {
    u64 r; asm("fma.rn.f32x2 %0, %1, %2, %3;" : "=l"(r) : "l"(a), "l"(b), "l"(c)); return r;
}
__device__ __forceinline__ u64 mul2(u64 a, u64 b) {
    u64 r; asm("mul.rn.f32x2 %0, %1, %2;" : "=l"(r) : "l"(a), "l"(b)); return r;
}
__device__ __forceinline__ float sqapx(float x) {
    float r; asm("sqrt.approx.f32 %0, %1;" : "=f"(r) : "f"(x)); return r;
}

__global__ void __launch_bounds__(128, 1)
garch_kernel(const float* __restrict__ z,
             const float* __restrict__ omega,
             const float* __restrict__ alpha,
             const float* __restrict__ beta,
             const float* __restrict__ mu,
             const float* __restrict__ sigma2_0,
             float* __restrict__ x)
{
    int n = blockIdx.x * blockDim.x + threadIdx.x;
    if (n >= GARCH_N) return;

    const float4* __restrict__ zp = (const float4*)(z + (size_t)n * GARCH_T * GARCH_D);
    float4* __restrict__ xp = (float4*)(x + (size_t)n * GARCH_T * GARCH_D);

    const u64 om2 = pk2(omega[0], omega[1]);
    const u64 al2 = pk2(alpha[0], alpha[1]);
    const u64 be2 = pk2(beta[0], beta[1]);
    const float m0 = mu[0], m1 = mu[1];

    // Carried state: s2 = clamped sigma2_{t-1}; fc = alpha*z^2_{t-1} + beta.
    // Initial: sigma2_prev = sigma2_0, eps2_prev = 0 -> fc = beta.
    u64 s2 = pk2(sigma2_0[0], sigma2_0[1]);
    u64 fc = be2;

    // Prefetch ring: PF iterations ahead, 2 float4 per iteration (32B/iter).
    float4 pa[PF], pb[PF];
#pragma unroll
    for (int i = 0; i < PF; i++) {
        pa[i] = zp[2 * i];
        pb[i] = zp[2 * i + 1];
    }

    for (int i = 0; i < NIT; i += PF) {
#pragma unroll
        for (int k = 0; k < PF; k++) {
            const float4 za = pa[k];
            const float4 zb = pb[k];
            // issue next prefetch early (independent of the chain)
            const int nxt = i + k + PF;
            if (nxt < NIT) {
                pa[k] = zp[2 * nxt];
                pb[k] = zp[2 * nxt + 1];
            }

            float4 xa, xb;

            // ---- step macro: one time step, both dims packed ----
#define GSTEP(z0, z1, o0, o1)                                        \
            {                                                        \
                s2 = fma2(s2, fc, om2);                              \
                float lo, hi;                                        \
                upk2(s2, lo, hi);                                    \
                lo = fmaxf(lo, 1e-12f);                              \
                hi = fmaxf(hi, 1e-12f);                              \
                s2 = pk2(lo, hi);                                    \
                const u64 zz = pk2(z0, z1);                          \
                fc = fma2(al2, mul2(zz, zz), be2);                   \
                const float sq0 = sqapx(lo);                         \
                const float sq1 = sqapx(hi);                         \
                o0 = fmaf(sq0, (z0), m0);                            \
                o1 = fmaf(sq1, (z1), m1);                            \
            }

            GSTEP(za.x, za.y, xa.x, xa.y)   // t0
            GSTEP(za.z, za.w, xa.z, xa.w)   // t0+1
            GSTEP(zb.x, zb.y, xb.x, xb.y)   // t0+2
            GSTEP(zb.z, zb.w, xb.z, xb.w)   // t0+3
#undef GSTEP

            xp[2 * (i + k)]     = xa;
            xp[2 * (i + k) + 1] = xb;
        }
    }
}

extern "C" void kernel_launch(void* const* d_in, const int* in_sizes, int n_in,
                              void* d_out, int out_size)
{
    const float* z        = (const float*)d_in[0];
    const float* omega    = (const float*)d_in[1];
    const float* alpha    = (const float*)d_in[2];
    const float* beta     = (const float*)d_in[3];
    const float* mu       = (const float*)d_in[4];
    const float* sigma2_0 = (const float*)d_in[5];
    float* x = (float*)d_out;

    const int threads = 128;
    const int blocks  = GARCH_N / threads;   // 256
    garch_kernel<<<blocks, threads>>>(z, omega, alpha, beta, mu, sigma2_0, x);
}

// round 4
// speedup vs baseline: 1.1892x; 1.1892x over previous
#include <cuda_runtime.h>
#include <cstdint>

// GARCH(1,1) path generation, smem-staged coalesced version.
//
// Round-1 kernel was L1tex-wavefront bound: per-thread private 16KB chain rows
// made every warp LDG/STG touch 32 distinct lines (32 wavefronts vs 4 ideal).
// Fix: stage z/x tiles through shared memory.
//   - cp.async cooperative loads: 8 lanes cover one chain's contiguous 128B
//     chunk -> 4 lines per warp-load (8x fewer wavefronts).
//   - compute threads read their own chain from smem (XOR-swizzled, LDS.128
//     conflict-free) and run the recurrence in registers.
//   - outputs staged in smem, then cooperatively stored coalesced.
//
// sigma2_t = omega + sigma2_{t-1} * (alpha*z_{t-1}^2 + beta)
// x_t = mu + sqrt(max(sigma2_t, 1e-12)) * z_t

#define GARCH_N 32768
#define GARCH_T 2048
#define GARCH_D 2
#define ROW_BYTES (GARCH_T * GARCH_D * 4)   // 16384 bytes per chain

#define CH     128                 // chains per CTA (= threads per CTA)
#define TC     16                  // timesteps per stage
#define CHUNK  (TC * GARCH_D * 4)  // 128 bytes per chain per stage
#define NSTAGE (GARCH_T / TC)      // 128 stages
#define DEPTH  3                   // input pipeline depth

#define TILE_BYTES (CH * CHUNK)                       // 16 KB
#define SMEM_BYTES (TILE_BYTES * (DEPTH + 2))         // 3 in + 2 out = 80 KB

typedef unsigned long long u64;

__device__ __forceinline__ u64 pk2(float lo, float hi) {
    u64 r; asm("mov.b64 %0, {%1, %2};" : "=l"(r) : "f"(lo), "f"(hi)); return r;
}
__device__ __forceinline__ void upk2(u64 v, float& lo, float& hi) {
    asm("mov.b64 {%0, %1}, %2;" : "=f"(lo), "=f"(hi) : "l"(v));
}
__device__ __forceinline__ u64 fma2(u64 a, u64 b, u64 c) {
    u64 r; asm("fma.rn.f32x2 %0, %1, %2, %3;" : "=l"(r) : "l"(a), "l"(b), "l"(c)); return r;
}
__device__ __forceinline__ u64 mul2(u64 a, u64 b) {
    u64 r; asm("mul.rn.f32x2 %0, %1, %2;" : "=l"(r) : "l"(a), "l"(b)); return r;
}
__device__ __forceinline__ float sqapx(float x) {
    float r; asm("sqrt.approx.f32 %0, %1;" : "=f"(r) : "f"(x)); return r;
}

// byte offset of (chain c, 16B-chunk j) within a tile; XOR-8 swizzle keeps
// both the per-chain compute access (fixed c, j=0..7) and the cooperative
// access (8 lanes sweep j for one c) conflict-free for LDS/STS.128.
__device__ __forceinline__ int swz(int c, int j) {
    return c * CHUNK + ((j ^ (c & 7)) << 4);
}

__device__ __forceinline__ void cp_async16(char* smem_dst, const char* gsrc) {
    unsigned saddr = (unsigned)__cvta_generic_to_shared(smem_dst);
    asm volatile("cp.async.cg.shared.global [%0], [%1], 16;\n"
                 :: "r"(saddr), "l"(gsrc));
}
__device__ __forceinline__ void cp_commit() {
    asm volatile("cp.async.commit_group;\n");
}
__device__ __forceinline__ void cp_wait() {
    asm volatile("cp.async.wait_group %0;\n" :: "n"(DEPTH - 1));
}

__global__ void __launch_bounds__(CH, 2)
garch_kernel(const float* __restrict__ z,
             const float* __restrict__ omega,
             const float* __restrict__ alpha,
             const float* __restrict__ beta,
             const float* __restrict__ mu,
             const float* __restrict__ sigma2_0,
             float* __restrict__ x)
{
    extern __shared__ char smem[];
    char* inb[DEPTH];
#pragma unroll
    for (int i = 0; i < DEPTH; i++) inb[i] = smem + i * TILE_BYTES;
    char* outb0 = smem + DEPTH * TILE_BYTES;
    char* outb1 = outb0 + TILE_BYTES;

    const int tid = threadIdx.x;
    const size_t chain_base = (size_t)blockIdx.x * CH;
    const char* zg = (const char*)z + chain_base * ROW_BYTES;
    char*       xg = (char*)x       + chain_base * ROW_BYTES;

    // cooperative-transfer mapping: thread tid, round k -> chunk (c, j)
    // chunkid = tid + CH*k ; c = chunkid/8 ; j = chunkid%8
    // 8 consecutive lanes cover one chain's contiguous 128B (one line).

    // ---- prologue: fill DEPTH input stages ----
#pragma unroll
    for (int sp = 0; sp < DEPTH; sp++) {
#pragma unroll
        for (int k = 0; k < 8; k++) {
            int chunkid = tid + CH * k;
            int c = chunkid >> 3, j = chunkid & 7;
            cp_async16(inb[sp] + swz(c, j),
                       zg + (size_t)c * ROW_BYTES + sp * CHUNK + j * 16);
        }
        cp_commit();
    }

    // ---- per-chain recurrence state ----
    const u64 om2 = pk2(omega[0], omega[1]);
    const u64 al2 = pk2(alpha[0], alpha[1]);
    const u64 be2 = pk2(beta[0], beta[1]);
    const float m0 = mu[0], m1 = mu[1];
    u64 s2 = pk2(sigma2_0[0], sigma2_0[1]);
    u64 fc = be2;

    for (int s = 0; s < NSTAGE; s++) {
        cp_wait();
        __syncthreads();

        const char* ib = inb[s % DEPTH];
        char* ob = (s & 1) ? outb1 : outb0;

        // ---- compute 16 timesteps for this thread's chain ----
#pragma unroll
        for (int j = 0; j < 8; j++) {
            const float4 za = *(const float4*)(ib + swz(tid, j));
            float4 xa;
#define GSTEP(z0, z1, o0, o1)                                        \
            {                                                        \
                s2 = fma2(s2, fc, om2);                              \
                float lo, hi;                                        \
                upk2(s2, lo, hi);                                    \
                lo = fmaxf(lo, 1e-12f);                              \
                hi = fmaxf(hi, 1e-12f);                              \
                s2 = pk2(lo, hi);                                    \
                const u64 zz = pk2(z0, z1);                          \
                fc = fma2(al2, mul2(zz, zz), be2);                   \
                o0 = fmaf(sqapx(lo), (z0), m0);                      \
                o1 = fmaf(sqapx(hi), (z1), m1);                      \
            }
            GSTEP(za.x, za.y, xa.x, xa.y)
            GSTEP(za.z, za.w, xa.z, xa.w)
#undef GSTEP
            *(float4*)(ob + swz(tid, j)) = xa;
        }

        __syncthreads();   // tile consumed + out tile complete

        // ---- prefetch stage s+DEPTH into the buffer just freed ----
        const int sp = s + DEPTH;
        if (sp < NSTAGE) {
#pragma unroll
            for (int k = 0; k < 8; k++) {
                int chunkid = tid + CH * k;
                int c = chunkid >> 3, j = chunkid & 7;
                cp_async16(inb[s % DEPTH] + swz(c, j),
                           zg + (size_t)c * ROW_BYTES + (size_t)sp * CHUNK + j * 16);
            }
        }
        cp_commit();   // always commit (keeps wait_group bookkeeping exact)

        // ---- cooperative coalesced store of the out tile ----
#pragma unroll
        for (int k = 0; k < 8; k++) {
            int chunkid = tid + CH * k;
            int c = chunkid >> 3, j = chunkid & 7;
            const float4 v = *(const float4*)(ob + swz(c, j));
            *(float4*)(xg + (size_t)c * ROW_BYTES + (size_t)s * CHUNK + j * 16) = v;
        }
    }
}

extern "C" void kernel_launch(void* const* d_in, const int* in_sizes, int n_in,
                              void* d_out, int out_size)
{
    const float* z        = (const float*)d_in[0];
    const float* omega    = (const float*)d_in[1];
    const float* alpha    = (const float*)d_in[2];
    const float* beta     = (const float*)d_in[3];
    const float* mu       = (const float*)d_in[4];
    const float* sigma2_0 = (const float*)d_in[5];
    float* x = (float*)d_out;

    cudaFuncSetAttribute(garch_kernel,
                         cudaFuncAttributeMaxDynamicSharedMemorySize, SMEM_BYTES);

    const int blocks = GARCH_N / CH;   // 256
    garch_kernel<<<blocks, CH, SMEM_BYTES>>>(z, omega, alpha, beta, mu, sigma2_0, x);
}